// round 1
// baseline (speedup 1.0000x reference)
#include <cuda_runtime.h>
#include <stdint.h>

#define BATCH 128
#define N_RX 34
#define IMG_H 512
#define IMG_W 512
#define N_PTS (BATCH * N_RX)

// ---------------------------------------------------------------------------
// Kernel 1: zero the 256MB output with 16B vector stores (HBM-write bound).
// ---------------------------------------------------------------------------
__global__ void zero_kernel(float4* __restrict__ out, int n4) {
    int i = blockIdx.x * blockDim.x + threadIdx.x;
    if (i < n4) {
        out[i] = make_float4(0.f, 0.f, 0.f, 0.f);
    }
}

// ---------------------------------------------------------------------------
// Kernel 2: scatter 4352 points. One thread per (batch, rx).
// Last-wins duplicate semantics: skip write if a LATER rx in the same batch
// maps to the same pixel.
// ---------------------------------------------------------------------------
__global__ void scatter_kernel(const float* __restrict__ x_vecs,
                               const float* __restrict__ dw,
                               const float* __restrict__ db,
                               const float* __restrict__ cw,
                               const float* __restrict__ cb,
                               float* __restrict__ out) {
    int t = blockIdx.x * blockDim.x + threadIdx.x;
    if (t >= N_PTS) return;

    int b = t / N_RX;
    int r = t % N_RX;

    const float4 v = *reinterpret_cast<const float4*>(x_vecs + (size_t)t * 4);
    float raw = v.x;
    float mask = (raw != 0.0f) ? 1.0f : 0.0f;

    float p = raw * dw[r] + mask * db[r];
    int cat = (int)v.w;
    p = p * cw[cat] + mask * cb[cat];

    int xx = (int)rintf(v.y);   // col 1 -> x
    int yy = (int)rintf(v.z);   // col 2 -> y

    // Last-wins: if any later point in this batch targets the same pixel, skip.
    const float* batch_base = x_vecs + (size_t)b * N_RX * 4;
    for (int rr = r + 1; rr < N_RX; rr++) {
        int x2 = (int)rintf(batch_base[rr * 4 + 1]);
        int y2 = (int)rintf(batch_base[rr * 4 + 2]);
        if (x2 == xx && y2 == yy) return;
    }

    size_t base = ((size_t)b * 2) * IMG_H * IMG_W + (size_t)yy * IMG_W + xx;
    out[base] = p;                                 // channel 0
    out[base + (size_t)IMG_H * IMG_W] = raw;       // channel 1
}

// ---------------------------------------------------------------------------
extern "C" void kernel_launch(void* const* d_in, const int* in_sizes, int n_in,
                              void* d_out, int out_size) {
    const float* x_vecs = (const float*)d_in[0];
    const float* dw     = (const float*)d_in[1];
    const float* db     = (const float*)d_in[2];
    const float* cw     = (const float*)d_in[3];
    const float* cb     = (const float*)d_in[4];
    float* out = (float*)d_out;

    int n4 = out_size / 4;   // 16,777,216 float4
    zero_kernel<<<(n4 + 255) / 256, 256>>>(reinterpret_cast<float4*>(out), n4);

    scatter_kernel<<<(N_PTS + 127) / 128, 128>>>(x_vecs, dw, db, cw, cb, out);
}